// round 16
// baseline (speedup 1.0000x reference)
#include <cuda_runtime.h>
#include <cuda_fp16.h>
#include <mma.h>
#include <math.h>
#include <cstdint>

using namespace nvcuda;

#define DD 64
#define NMAX 50000
#define EMAX 800000
#define INV_SQRT2 0.70710678118654752440f

typedef unsigned int u32;

// ---- scratch (device globals: allocation-free) ----
__device__ __half g_embh[(size_t)EMAX * DD]; // bond output fp16, natural edge order
__device__ float g_agg[(size_t)NMAX * DD];   // scatter-add target
__device__ float g_h[(size_t)NMAX * DD];     // MLP output (pre-BN)
__device__ float g_xa[(size_t)NMAX * DD];    // x ping
__device__ float g_xb[(size_t)NMAX * DD];    // x pong
__device__ float g_bsum[3][DD];              // BN sum per layer/feature
__device__ float g_bsq[3][DD];               // BN sumsq per layer/feature

__device__ __forceinline__ float gelu_exact(float v) {
    return 0.5f * v * (1.0f + erff(v * 0.70710678118654752440f));
}

__device__ __forceinline__ const float* sel_in(int s, const float* ext) {
    return (s == 0) ? ext : ((s == 1) ? g_xa : g_xb);
}
__device__ __forceinline__ float* sel_out(int s, float* ext) {
    return (s == 0) ? ext : ((s == 1) ? g_xa : g_xb);
}

// ---- raw mma helpers ----
__device__ __forceinline__ u32 smem_u32(const void* p) {
    return (u32)__cvta_generic_to_shared(p);
}
__device__ __forceinline__ void ldsm_x4(u32& r0, u32& r1, u32& r2, u32& r3, u32 a) {
    asm volatile("ldmatrix.sync.aligned.m8n8.x4.shared.b16 {%0,%1,%2,%3}, [%4];"
                 : "=r"(r0), "=r"(r1), "=r"(r2), "=r"(r3) : "r"(a));
}
__device__ __forceinline__ void ldsm_x4_t(u32& r0, u32& r1, u32& r2, u32& r3, u32 a) {
    asm volatile("ldmatrix.sync.aligned.m8n8.x4.trans.shared.b16 {%0,%1,%2,%3}, [%4];"
                 : "=r"(r0), "=r"(r1), "=r"(r2), "=r"(r3) : "r"(a));
}
__device__ __forceinline__ void mma16816(float* c, const u32* a, u32 bb0, u32 bb1) {
    asm volatile(
        "mma.sync.aligned.m16n8k16.row.col.f32.f16.f16.f32 "
        "{%0,%1,%2,%3}, {%4,%5,%6,%7}, {%8,%9}, {%0,%1,%2,%3};"
        : "+f"(c[0]), "+f"(c[1]), "+f"(c[2]), "+f"(c[3])
        : "r"(a[0]), "r"(a[1]), "r"(a[2]), "r"(a[3]), "r"(bb0), "r"(bb1));
}

// ============================================================
// K_bond (wmma): emb = attr @ W_be + b_be -> fp16  (R8-proven, unchanged)
// ============================================================
__global__ void __launch_bounds__(256) k_bond(
    const float* __restrict__ attr,
    const float* __restrict__ Wbe,
    const float* __restrict__ bbe, int E)
{
    __shared__ __half As[128][72];
    __shared__ __half Ws[64][72];
    __shared__ float  Cs[8][16][16];

    int tid  = threadIdx.x;
    int warp = tid >> 5;
    int lane = tid & 31;

    for (int i = tid; i < 64 * 64; i += 256) {
        Ws[i >> 6][i & 63] = __float2half_rn(Wbe[i]);
    }

    float bias[4][8];
#pragma unroll
    for (int n = 0; n < 4; n++) {
#pragma unroll
        for (int j = 0; j < 8; j++) {
            bias[n][j] = bbe[n * 16 + (lane & 1) * 8 + j];
        }
    }
    __syncthreads();

    for (int base = blockIdx.x * 128; base < E; base += gridDim.x * 128) {
        for (int i = tid; i < 128 * 16; i += 256) {
            int rr = i >> 4, c4 = i & 15;
            int row = base + rr;
            float4 v = (row < E) ? ((const float4*)attr)[(size_t)row * 16 + c4]
                                 : make_float4(0.f, 0.f, 0.f, 0.f);
            __half2* dsty = (__half2*)&As[rr][c4 * 4];
            dsty[0] = __floats2half2_rn(v.x, v.y);
            dsty[1] = __floats2half2_rn(v.z, v.w);
        }
        __syncthreads();

        wmma::fragment<wmma::accumulator, 16, 16, 16, float> acc[4];
#pragma unroll
        for (int n = 0; n < 4; n++) {
            wmma::fill_fragment(acc[n], 0.0f);
        }

#pragma unroll
        for (int k = 0; k < 4; k++) {
            wmma::fragment<wmma::matrix_a, 16, 16, 16, __half, wmma::row_major> af;
            wmma::load_matrix_sync(af, &As[warp * 16][k * 16], 72);
#pragma unroll
            for (int n = 0; n < 4; n++) {
                wmma::fragment<wmma::matrix_b, 16, 16, 16, __half, wmma::row_major> bf;
                wmma::load_matrix_sync(bf, &Ws[k * 16][n * 16], 72);
                wmma::mma_sync(acc[n], af, bf, acc[n]);
            }
        }

#pragma unroll
        for (int n = 0; n < 4; n++) {
            wmma::store_matrix_sync(&Cs[warp][0][0], acc[n], 16, wmma::mem_row_major);
            __syncwarp();
            int r_in = lane >> 1;
            int hsel = lane & 1;
            int row  = base + warp * 16 + r_in;
            if (row < E) {
                const float* csrc = &Cs[warp][r_in][hsel * 8];
                __half tmp[8];
#pragma unroll
                for (int j = 0; j < 8; j++) {
                    tmp[j] = __float2half_rn(csrc[j] + bias[n][j]);
                }
                int d0 = n * 16 + hsel * 8;
                *(uint4*)(&g_embh[(size_t)row * DD + d0]) = *(uint4*)tmp;
            }
            __syncwarp();
        }
        __syncthreads();
    }
}

// ============================================================
// K_zero: zero agg + BN stats  (R9-proven)
// ============================================================
__global__ void k_zero(int N)
{
    int idx = blockIdx.x * blockDim.x + threadIdx.x;
    if (idx < N * 16) {
        ((float4*)g_agg)[idx] = make_float4(0.f, 0.f, 0.f, 0.f);
    }
    if (blockIdx.x == 0 && threadIdx.x < 3 * DD) {
        ((float*)g_bsum)[threadIdx.x] = 0.f;
        ((float*)g_bsq)[threadIdx.x]  = 0.f;
    }
}

// ============================================================
// K_msg: agg[dst] += gelu(x[src] + emb)   (R6/R9-proven, 8-dim/thread)
// ============================================================
__global__ void k_msg(int xsel, const float* __restrict__ xext,
                      const int* __restrict__ src,
                      const int* __restrict__ dst, int E)
{
    int idx = blockIdx.x * blockDim.x + threadIdx.x;
    if (idx >= E * 8) return;
    const float* x = sel_in(xsel, xext);
    int e = idx >> 3, q = idx & 7;
    int s = src[e], t = dst[e];

    uint4 eh = ((const uint4*)g_embh)[(size_t)e * 8 + q];
    float2 e0 = __half22float2(*(__half2*)&eh.x);
    float2 e1 = __half22float2(*(__half2*)&eh.y);
    float2 e2 = __half22float2(*(__half2*)&eh.z);
    float2 e3 = __half22float2(*(__half2*)&eh.w);

    float4 x0 = ((const float4*)x)[(size_t)s * 16 + q * 2];
    float4 x1 = ((const float4*)x)[(size_t)s * 16 + q * 2 + 1];

    float4 m0, m1;
    m0.x = gelu_exact(e0.x + x0.x);
    m0.y = gelu_exact(e0.y + x0.y);
    m0.z = gelu_exact(e1.x + x0.z);
    m0.w = gelu_exact(e1.y + x0.w);
    m1.x = gelu_exact(e2.x + x1.x);
    m1.y = gelu_exact(e2.y + x1.y);
    m1.z = gelu_exact(e3.x + x1.z);
    m1.w = gelu_exact(e3.y + x1.w);

    float4* p = ((float4*)g_agg) + (size_t)t * 16 + q * 2;
#if defined(__CUDA_ARCH__) && (__CUDA_ARCH__ >= 900)
    atomicAdd(p,     m0);
    atomicAdd(p + 1, m1);
#else
    float* pf = (float*)p;
    atomicAdd(pf + 0, m0.x); atomicAdd(pf + 1, m0.y);
    atomicAdd(pf + 2, m0.z); atomicAdd(pf + 3, m0.w);
    atomicAdd(pf + 4, m1.x); atomicAdd(pf + 5, m1.y);
    atomicAdd(pf + 6, m1.z); atomicAdd(pf + 7, m1.w);
#endif
}

// ============================================================
// K_mlp (raw mma): h = gelu(((1+eps)x + agg) @ W1 + b1) @ W2 + b2
// R14 register-resident fragment hand-off + fused BN stats:
// per-thread ls/lq register accumulators over epilogue2 values,
// flushed ONCE at kernel end (smem atomics -> 64 global REDs).
// ============================================================
__global__ void __launch_bounds__(256) k_mlp(
    int xsel, const float* __restrict__ xext,
    const float* __restrict__ W1, const float* __restrict__ b1,
    const float* __restrict__ W2, const float* __restrict__ b2,
    const float* __restrict__ epsp, int layer, int N)
{
    __shared__ __half As[128][72];
    __shared__ __half W1s[64][72];
    __shared__ __half W2s[64][72];
    __shared__ float  b1s[DD];
    __shared__ float  b2s[DD];
    __shared__ float  sS[DD];
    __shared__ float  sQ[DD];

    int tid  = threadIdx.x;
    int warp = tid >> 5;
    int lane = tid & 31;

    for (int i = tid; i < 64 * 64; i += 256) {
        W1s[i >> 6][i & 63] = __float2half_rn(W1[i]);
        W2s[i >> 6][i & 63] = __float2half_rn(W2[i]);
    }
    if (tid < DD) {
        b1s[tid] = b1[tid];
        b2s[tid] = b2[tid];
        sS[tid]  = 0.f;
        sQ[tid]  = 0.f;
    }

    float eps1 = 1.0f + epsp[layer];
    const float* x = sel_in(xsel, xext);
    __syncthreads();

    int qrow = lane >> 2;          // 0..7
    int qcol = (lane & 3) * 2;     // 0,2,4,6

    // per-thread BN stat accumulators: slot n*2+half -> column (n*8+qcol+half)
    float ls[16];
    float lq[16];
#pragma unroll
    for (int i = 0; i < 16; i++) {
        ls[i] = 0.f;
        lq[i] = 0.f;
    }

    for (int base = blockIdx.x * 128; base < N; base += gridDim.x * 128) {
        // ---- stage input (1+eps)x + agg -> fp16 ----
        for (int i = tid; i < 128 * 16; i += 256) {
            int rr = i >> 4, c4 = i & 15;
            int row = base + rr;
            float4 v = make_float4(0.f, 0.f, 0.f, 0.f);
            if (row < N) {
                float4 xv = ((const float4*)x)[(size_t)row * 16 + c4];
                float4 av = ((const float4*)g_agg)[(size_t)row * 16 + c4];
                v.x = fmaf(eps1, xv.x, av.x);
                v.y = fmaf(eps1, xv.y, av.y);
                v.z = fmaf(eps1, xv.z, av.z);
                v.w = fmaf(eps1, xv.w, av.w);
            }
            __half2* dsty = (__half2*)&As[rr][c4 * 4];
            dsty[0] = __floats2half2_rn(v.x, v.y);
            dsty[1] = __floats2half2_rn(v.z, v.w);
        }
        __syncthreads();

        float c1[8][4];
        u32 a1[4][4];
        {
            // ---- GEMM1 ----
#pragma unroll
            for (int k = 0; k < 4; k++) {
                u32 addr = smem_u32(&As[warp * 16 + (lane & 15)][k * 16 + (lane >> 4) * 8]);
                ldsm_x4(a1[k][0], a1[k][1], a1[k][2], a1[k][3], addr);
            }
#pragma unroll
            for (int n = 0; n < 8; n++) {
#pragma unroll
                for (int j = 0; j < 4; j++) {
                    c1[n][j] = 0.f;
                }
            }
#pragma unroll
            for (int k = 0; k < 4; k++) {
#pragma unroll
                for (int n2 = 0; n2 < 4; n2++) {
                    u32 f0, f1, f2, f3;
                    u32 addr = smem_u32(&W1s[k * 16 + (lane & 15)][n2 * 16 + (lane >> 4) * 8]);
                    ldsm_x4_t(f0, f1, f2, f3, addr);
                    mma16816(c1[2 * n2],     a1[k], f0, f1);
                    mma16816(c1[2 * n2 + 1], a1[k], f2, f3);
                }
            }
        }

        // ---- epilogue1 in registers: gelu(c1 + b1) -> A fragments of GEMM2 ----
        u32 a2[4][4];
#pragma unroll
        for (int n = 0; n < 8; n++) {
            float g0 = b1s[n * 8 + qcol];
            float g1 = b1s[n * 8 + qcol + 1];
            float t0 = gelu_exact(c1[n][0] + g0);
            float t1 = gelu_exact(c1[n][1] + g1);
            float t2 = gelu_exact(c1[n][2] + g0);
            float t3 = gelu_exact(c1[n][3] + g1);
            __half2 p01 = __floats2half2_rn(t0, t1);
            __half2 p23 = __floats2half2_rn(t2, t3);
            a2[n >> 1][(n & 1) * 2 + 0] = *(u32*)&p01;
            a2[n >> 1][(n & 1) * 2 + 1] = *(u32*)&p23;
        }

        float c2[8][4];
        {
            // ---- GEMM2 ----
#pragma unroll
            for (int n = 0; n < 8; n++) {
#pragma unroll
                for (int j = 0; j < 4; j++) {
                    c2[n][j] = 0.f;
                }
            }
#pragma unroll
            for (int k = 0; k < 4; k++) {
#pragma unroll
                for (int n2 = 0; n2 < 4; n2++) {
                    u32 f0, f1, f2, f3;
                    u32 addr = smem_u32(&W2s[k * 16 + (lane & 15)][n2 * 16 + (lane >> 4) * 8]);
                    ldsm_x4_t(f0, f1, f2, f3, addr);
                    mma16816(c2[2 * n2],     a2[k], f0, f1);
                    mma16816(c2[2 * n2 + 1], a2[k], f2, f3);
                }
            }
        }

        // ---- epilogue2: + b2, float2 stores to g_h, register BN stats ----
        {
            int row0 = base + warp * 16 + qrow;
            int row1 = row0 + 8;
#pragma unroll
            for (int n = 0; n < 8; n++) {
                int col = n * 8 + qcol;
                float g0 = b2s[col];
                float g1 = b2s[col + 1];
                if (row0 < N) {
                    float o0 = c2[n][0] + g0;
                    float o1 = c2[n][1] + g1;
                    *(float2*)&g_h[(size_t)row0 * DD + col] = make_float2(o0, o1);
                    ls[n * 2 + 0] += o0;
                    lq[n * 2 + 0] = fmaf(o0, o0, lq[n * 2 + 0]);
                    ls[n * 2 + 1] += o1;
                    lq[n * 2 + 1] = fmaf(o1, o1, lq[n * 2 + 1]);
                }
                if (row1 < N) {
                    float o2 = c2[n][2] + g0;
                    float o3 = c2[n][3] + g1;
                    *(float2*)&g_h[(size_t)row1 * DD + col] = make_float2(o2, o3);
                    ls[n * 2 + 0] += o2;
                    lq[n * 2 + 0] = fmaf(o2, o2, lq[n * 2 + 0]);
                    ls[n * 2 + 1] += o3;
                    lq[n * 2 + 1] = fmaf(o3, o3, lq[n * 2 + 1]);
                }
            }
        }
        __syncthreads();   // protect As before next tile's staging
    }

    // ---- flush BN stats: registers -> smem -> global ----
#pragma unroll
    for (int i = 0; i < 16; i++) {
        int col = (i >> 1) * 8 + qcol + (i & 1);
        atomicAdd(&sS[col], ls[i]);
        atomicAdd(&sQ[col], lq[i]);
    }
    __syncthreads();
    if (tid < DD) {
        atomicAdd(&g_bsum[layer][tid], sS[tid]);
        atomicAdd(&g_bsq[layer][tid],  sQ[tid]);
    }
}

// ============================================================
// K_bn: x_next = (x + gelu(BN(h))) * INV_SQRT2 ; zero agg for next layer
// (R9-proven, unchanged)
// ============================================================
__global__ void k_bn(int xsel, const float* __restrict__ xext,
                     int osel, float* __restrict__ oext,
                     const float* __restrict__ gamma,
                     const float* __restrict__ beta, int layer, int N)
{
    int idx = blockIdx.x * blockDim.x + threadIdx.x;
    if (idx >= N * 16) return;
    const float* xin = sel_in(xsel, xext);
    float* xout = sel_out(osel, oext);

    int q = idx & 15;
    float invN = 1.0f / (float)N;
    float4 hv = ((const float4*)g_h)[idx];
    float4 xv = ((const float4*)xin)[idx];
    float hvv[4] = {hv.x, hv.y, hv.z, hv.w};
    float xvv[4] = {xv.x, xv.y, xv.z, xv.w};
    float o[4];
#pragma unroll
    for (int j = 0; j < 4; j++) {
        int dd = q * 4 + j;
        float mu   = g_bsum[layer][dd] * invN;
        float var  = g_bsq[layer][dd] * invN - mu * mu;
        float rstd = rsqrtf(var + 1e-5f);
        float hn   = (hvv[j] - mu) * rstd * gamma[dd] + beta[dd];
        o[j] = (xvv[j] + gelu_exact(hn)) * INV_SQRT2;
    }
    ((float4*)xout)[idx] = make_float4(o[0], o[1], o[2], o[3]);
    ((float4*)g_agg)[idx] = make_float4(0.f, 0.f, 0.f, 0.f);
}

// ============================================================
// launcher
// ============================================================
extern "C" void kernel_launch(void* const* d_in, const int* in_sizes, int n_in,
                              void* d_out, int out_size)
{
    const float* x0    = (const float*)d_in[0];
    const int*   eidx  = (const int*)  d_in[1];
    const float* eattr = (const float*)d_in[2];
    const float* Wbe   = (const float*)d_in[3];
    const float* bbe   = (const float*)d_in[4];
    const float* epsp  = (const float*)d_in[5];
    const float* W1    = (const float*)d_in[6];
    const float* b1    = (const float*)d_in[7];
    const float* W2    = (const float*)d_in[8];
    const float* b2    = (const float*)d_in[9];
    const float* gamma = (const float*)d_in[10];
    const float* beta  = (const float*)d_in[11];

    int N = in_sizes[0] / DD;
    int E = in_sizes[1] / 2;
    const int* src = eidx;
    const int* dst = eidx + E;

    k_zero<<<(N * 16 + 255) / 256, 256>>>(N);
    k_bond<<<(E + 127) / 128, 256>>>(eattr, Wbe, bbe, E);

    int in_sel[3]  = {0, 1, 2};
    int out_sel[3] = {1, 2, 0};

    int nblk_node = (N * 16 + 255) / 256;
    int nblk_edge = (E * 8 + 255) / 256;
    int nblk_mlp  = (N + 127) / 128;

    for (int l = 0; l < 3; l++) {
        const float* xext = (l == 0) ? x0 : nullptr;
        k_msg<<<nblk_edge, 256>>>(in_sel[l], xext, src, dst, E);
        k_mlp<<<nblk_mlp, 256>>>(in_sel[l], xext,
                                 W1 + (size_t)l * DD * DD, b1 + (size_t)l * DD,
                                 W2 + (size_t)l * DD * DD, b2 + (size_t)l * DD,
                                 epsp, l, N);
        k_bn <<<nblk_node, 256>>>(in_sel[l], xext, out_sel[l], (float*)d_out,
                                  gamma + (size_t)l * DD, beta + (size_t)l * DD, l, N);
    }
}

// round 17
// speedup vs baseline: 1.3746x; 1.3746x over previous
#include <cuda_runtime.h>
#include <cuda_fp16.h>
#include <mma.h>
#include <math.h>
#include <cstdint>

using namespace nvcuda;

#define DD 64
#define NMAX 50000
#define EMAX 800000
#define INV_SQRT2 0.70710678118654752440f

typedef unsigned int u32;

// ---- scratch (device globals: allocation-free) ----
__device__ __half g_embh[(size_t)EMAX * DD]; // bond output fp16, natural edge order
__device__ float g_agg[(size_t)NMAX * DD];   // scatter-add target
__device__ float g_h[(size_t)NMAX * DD];     // MLP output (pre-BN)
__device__ float g_xa[(size_t)NMAX * DD];    // x ping
__device__ float g_xb[(size_t)NMAX * DD];    // x pong
__device__ float g_bsum[3][DD];              // BN sum per layer/feature
__device__ float g_bsq[3][DD];               // BN sumsq per layer/feature

__device__ __forceinline__ float gelu_exact(float v) {
    return 0.5f * v * (1.0f + erff(v * 0.70710678118654752440f));
}

__device__ __forceinline__ const float* sel_in(int s, const float* ext) {
    return (s == 0) ? ext : ((s == 1) ? g_xa : g_xb);
}
__device__ __forceinline__ float* sel_out(int s, float* ext) {
    return (s == 0) ? ext : ((s == 1) ? g_xa : g_xb);
}

// ---- raw mma helpers ----
__device__ __forceinline__ u32 smem_u32(const void* p) {
    return (u32)__cvta_generic_to_shared(p);
}
__device__ __forceinline__ void ldsm_x4(u32& r0, u32& r1, u32& r2, u32& r3, u32 a) {
    asm volatile("ldmatrix.sync.aligned.m8n8.x4.shared.b16 {%0,%1,%2,%3}, [%4];"
                 : "=r"(r0), "=r"(r1), "=r"(r2), "=r"(r3) : "r"(a));
}
__device__ __forceinline__ void ldsm_x4_t(u32& r0, u32& r1, u32& r2, u32& r3, u32 a) {
    asm volatile("ldmatrix.sync.aligned.m8n8.x4.trans.shared.b16 {%0,%1,%2,%3}, [%4];"
                 : "=r"(r0), "=r"(r1), "=r"(r2), "=r"(r3) : "r"(a));
}
__device__ __forceinline__ void mma16816(float* c, const u32* a, u32 bb0, u32 bb1) {
    asm volatile(
        "mma.sync.aligned.m16n8k16.row.col.f32.f16.f16.f32 "
        "{%0,%1,%2,%3}, {%4,%5,%6,%7}, {%8,%9}, {%0,%1,%2,%3};"
        : "+f"(c[0]), "+f"(c[1]), "+f"(c[2]), "+f"(c[3])
        : "r"(a[0]), "r"(a[1]), "r"(a[2]), "r"(a[3]), "r"(bb0), "r"(bb1));
}

// ============================================================
// K_bond (raw mma): emb = attr @ W_be + b_be -> fp16, natural order.
// Same GEMM structure as k_mlp's GEMM1; epilogue stores half2-packed
// C fragments directly to gmem (no Cs smem round-trip).
// ============================================================
__global__ void __launch_bounds__(256) k_bond(
    const float* __restrict__ attr,
    const float* __restrict__ Wbe,
    const float* __restrict__ bbe, int E)
{
    __shared__ __half As[128][72];
    __shared__ __half Ws[64][72];
    __shared__ float  bbs[DD];

    int tid  = threadIdx.x;
    int warp = tid >> 5;
    int lane = tid & 31;

    for (int i = tid; i < 64 * 64; i += 256) {
        Ws[i >> 6][i & 63] = __float2half_rn(Wbe[i]);
    }
    if (tid < DD) {
        bbs[tid] = bbe[tid];
    }
    __syncthreads();

    int qrow = lane >> 2;          // 0..7
    int qcol = (lane & 3) * 2;     // 0,2,4,6

    for (int base = blockIdx.x * 128; base < E; base += gridDim.x * 128) {
        // ---- stage attr tile -> fp16 smem ----
        for (int i = tid; i < 128 * 16; i += 256) {
            int rr = i >> 4, c4 = i & 15;
            int row = base + rr;
            float4 v = (row < E) ? ((const float4*)attr)[(size_t)row * 16 + c4]
                                 : make_float4(0.f, 0.f, 0.f, 0.f);
            __half2* dsty = (__half2*)&As[rr][c4 * 4];
            dsty[0] = __floats2half2_rn(v.x, v.y);
            dsty[1] = __floats2half2_rn(v.z, v.w);
        }
        __syncthreads();

        // ---- GEMM ----
        u32 a1[4][4];
#pragma unroll
        for (int k = 0; k < 4; k++) {
            u32 addr = smem_u32(&As[warp * 16 + (lane & 15)][k * 16 + (lane >> 4) * 8]);
            ldsm_x4(a1[k][0], a1[k][1], a1[k][2], a1[k][3], addr);
        }
        float c1[8][4];
#pragma unroll
        for (int n = 0; n < 8; n++) {
#pragma unroll
            for (int j = 0; j < 4; j++) {
                c1[n][j] = 0.f;
            }
        }
#pragma unroll
        for (int k = 0; k < 4; k++) {
#pragma unroll
            for (int n2 = 0; n2 < 4; n2++) {
                u32 f0, f1, f2, f3;
                u32 addr = smem_u32(&Ws[k * 16 + (lane & 15)][n2 * 16 + (lane >> 4) * 8]);
                ldsm_x4_t(f0, f1, f2, f3, addr);
                mma16816(c1[2 * n2],     a1[k], f0, f1);
                mma16816(c1[2 * n2 + 1], a1[k], f2, f3);
            }
        }

        // ---- epilogue: + bias, pack half2, direct stores ----
        {
            int row0 = base + warp * 16 + qrow;
            int row1 = row0 + 8;
#pragma unroll
            for (int n = 0; n < 8; n++) {
                int col = n * 8 + qcol;
                float g0 = bbs[col];
                float g1 = bbs[col + 1];
                if (row0 < E) {
                    __half2 o = __floats2half2_rn(c1[n][0] + g0, c1[n][1] + g1);
                    *(__half2*)&g_embh[(size_t)row0 * DD + col] = o;
                }
                if (row1 < E) {
                    __half2 o = __floats2half2_rn(c1[n][2] + g0, c1[n][3] + g1);
                    *(__half2*)&g_embh[(size_t)row1 * DD + col] = o;
                }
            }
        }
        __syncthreads();
    }
}

// ============================================================
// K_zero: zero agg + BN stats  (R9-proven)
// ============================================================
__global__ void k_zero(int N)
{
    int idx = blockIdx.x * blockDim.x + threadIdx.x;
    if (idx < N * 16) {
        ((float4*)g_agg)[idx] = make_float4(0.f, 0.f, 0.f, 0.f);
    }
    if (blockIdx.x == 0 && threadIdx.x < 3 * DD) {
        ((float*)g_bsum)[threadIdx.x] = 0.f;
        ((float*)g_bsq)[threadIdx.x]  = 0.f;
    }
}

// ============================================================
// K_msg: agg[dst] += gelu(x[src] + emb)   (R6/R9-proven, 8-dim/thread)
// ============================================================
__global__ void k_msg(int xsel, const float* __restrict__ xext,
                      const int* __restrict__ src,
                      const int* __restrict__ dst, int E)
{
    int idx = blockIdx.x * blockDim.x + threadIdx.x;
    if (idx >= E * 8) return;
    const float* x = sel_in(xsel, xext);
    int e = idx >> 3, q = idx & 7;
    int s = src[e], t = dst[e];

    uint4 eh = ((const uint4*)g_embh)[(size_t)e * 8 + q];
    float2 e0 = __half22float2(*(__half2*)&eh.x);
    float2 e1 = __half22float2(*(__half2*)&eh.y);
    float2 e2 = __half22float2(*(__half2*)&eh.z);
    float2 e3 = __half22float2(*(__half2*)&eh.w);

    float4 x0 = ((const float4*)x)[(size_t)s * 16 + q * 2];
    float4 x1 = ((const float4*)x)[(size_t)s * 16 + q * 2 + 1];

    float4 m0, m1;
    m0.x = gelu_exact(e0.x + x0.x);
    m0.y = gelu_exact(e0.y + x0.y);
    m0.z = gelu_exact(e1.x + x0.z);
    m0.w = gelu_exact(e1.y + x0.w);
    m1.x = gelu_exact(e2.x + x1.x);
    m1.y = gelu_exact(e2.y + x1.y);
    m1.z = gelu_exact(e3.x + x1.z);
    m1.w = gelu_exact(e3.y + x1.w);

    float4* p = ((float4*)g_agg) + (size_t)t * 16 + q * 2;
#if defined(__CUDA_ARCH__) && (__CUDA_ARCH__ >= 900)
    atomicAdd(p,     m0);
    atomicAdd(p + 1, m1);
#else
    float* pf = (float*)p;
    atomicAdd(pf + 0, m0.x); atomicAdd(pf + 1, m0.y);
    atomicAdd(pf + 2, m0.z); atomicAdd(pf + 3, m0.w);
    atomicAdd(pf + 4, m1.x); atomicAdd(pf + 5, m1.y);
    atomicAdd(pf + 6, m1.z); atomicAdd(pf + 7, m1.w);
#endif
}

// ============================================================
// K_mlp (raw mma): h = gelu(((1+eps)x + agg) @ W1 + b1) @ W2 + b2
// (R14/R15-proven: register-resident fragment hand-off, unchanged)
// ============================================================
__global__ void __launch_bounds__(256) k_mlp(
    int xsel, const float* __restrict__ xext,
    const float* __restrict__ W1, const float* __restrict__ b1,
    const float* __restrict__ W2, const float* __restrict__ b2,
    const float* __restrict__ epsp, int layer, int N)
{
    __shared__ __half As[128][72];
    __shared__ __half W1s[64][72];
    __shared__ __half W2s[64][72];
    __shared__ float  b1s[DD];
    __shared__ float  b2s[DD];

    int tid  = threadIdx.x;
    int warp = tid >> 5;
    int lane = tid & 31;

    for (int i = tid; i < 64 * 64; i += 256) {
        W1s[i >> 6][i & 63] = __float2half_rn(W1[i]);
        W2s[i >> 6][i & 63] = __float2half_rn(W2[i]);
    }
    if (tid < DD) {
        b1s[tid] = b1[tid];
        b2s[tid] = b2[tid];
    }

    float eps1 = 1.0f + epsp[layer];
    const float* x = sel_in(xsel, xext);
    __syncthreads();

    int qrow = lane >> 2;          // 0..7
    int qcol = (lane & 3) * 2;     // 0,2,4,6

    for (int base = blockIdx.x * 128; base < N; base += gridDim.x * 128) {
        // ---- stage input (1+eps)x + agg -> fp16 ----
        for (int i = tid; i < 128 * 16; i += 256) {
            int rr = i >> 4, c4 = i & 15;
            int row = base + rr;
            float4 v = make_float4(0.f, 0.f, 0.f, 0.f);
            if (row < N) {
                float4 xv = ((const float4*)x)[(size_t)row * 16 + c4];
                float4 av = ((const float4*)g_agg)[(size_t)row * 16 + c4];
                v.x = fmaf(eps1, xv.x, av.x);
                v.y = fmaf(eps1, xv.y, av.y);
                v.z = fmaf(eps1, xv.z, av.z);
                v.w = fmaf(eps1, xv.w, av.w);
            }
            __half2* dsty = (__half2*)&As[rr][c4 * 4];
            dsty[0] = __floats2half2_rn(v.x, v.y);
            dsty[1] = __floats2half2_rn(v.z, v.w);
        }
        __syncthreads();

        float c1[8][4];
        u32 a1[4][4];
        {
            // ---- GEMM1 ----
#pragma unroll
            for (int k = 0; k < 4; k++) {
                u32 addr = smem_u32(&As[warp * 16 + (lane & 15)][k * 16 + (lane >> 4) * 8]);
                ldsm_x4(a1[k][0], a1[k][1], a1[k][2], a1[k][3], addr);
            }
#pragma unroll
            for (int n = 0; n < 8; n++) {
#pragma unroll
                for (int j = 0; j < 4; j++) {
                    c1[n][j] = 0.f;
                }
            }
#pragma unroll
            for (int k = 0; k < 4; k++) {
#pragma unroll
                for (int n2 = 0; n2 < 4; n2++) {
                    u32 f0, f1, f2, f3;
                    u32 addr = smem_u32(&W1s[k * 16 + (lane & 15)][n2 * 16 + (lane >> 4) * 8]);
                    ldsm_x4_t(f0, f1, f2, f3, addr);
                    mma16816(c1[2 * n2],     a1[k], f0, f1);
                    mma16816(c1[2 * n2 + 1], a1[k], f2, f3);
                }
            }
        }

        // ---- epilogue1 in registers: gelu(c1 + b1) -> A fragments of GEMM2 ----
        u32 a2[4][4];
#pragma unroll
        for (int n = 0; n < 8; n++) {
            float g0 = b1s[n * 8 + qcol];
            float g1 = b1s[n * 8 + qcol + 1];
            float t0 = gelu_exact(c1[n][0] + g0);
            float t1 = gelu_exact(c1[n][1] + g1);
            float t2 = gelu_exact(c1[n][2] + g0);
            float t3 = gelu_exact(c1[n][3] + g1);
            __half2 p01 = __floats2half2_rn(t0, t1);
            __half2 p23 = __floats2half2_rn(t2, t3);
            a2[n >> 1][(n & 1) * 2 + 0] = *(u32*)&p01;
            a2[n >> 1][(n & 1) * 2 + 1] = *(u32*)&p23;
        }

        float c2[8][4];
        {
            // ---- GEMM2 ----
#pragma unroll
            for (int n = 0; n < 8; n++) {
#pragma unroll
                for (int j = 0; j < 4; j++) {
                    c2[n][j] = 0.f;
                }
            }
#pragma unroll
            for (int k = 0; k < 4; k++) {
#pragma unroll
                for (int n2 = 0; n2 < 4; n2++) {
                    u32 f0, f1, f2, f3;
                    u32 addr = smem_u32(&W2s[k * 16 + (lane & 15)][n2 * 16 + (lane >> 4) * 8]);
                    ldsm_x4_t(f0, f1, f2, f3, addr);
                    mma16816(c2[2 * n2],     a2[k], f0, f1);
                    mma16816(c2[2 * n2 + 1], a2[k], f2, f3);
                }
            }
        }

        // ---- epilogue2: + b2, direct float2 stores to g_h ----
        {
            int row0 = base + warp * 16 + qrow;
            int row1 = row0 + 8;
#pragma unroll
            for (int n = 0; n < 8; n++) {
                int col = n * 8 + qcol;
                float g0 = b2s[col];
                float g1 = b2s[col + 1];
                if (row0 < N) {
                    float2 o = make_float2(c2[n][0] + g0, c2[n][1] + g1);
                    *(float2*)&g_h[(size_t)row0 * DD + col] = o;
                }
                if (row1 < N) {
                    float2 o = make_float2(c2[n][2] + g0, c2[n][3] + g1);
                    *(float2*)&g_h[(size_t)row1 * DD + col] = o;
                }
            }
        }
        __syncthreads();   // protect As before next tile's staging
    }
}

// ============================================================
// K_stat: column sums / sumsq of g_h -> BN stats  (R15-proven, vectorized)
// ============================================================
__global__ void __launch_bounds__(256) k_stat(int layer, int N)
{
    __shared__ float sS[DD];
    __shared__ float sQ[DD];
    int tid = threadIdx.x;
    if (tid < DD) {
        sS[tid] = 0.f;
        sQ[tid] = 0.f;
    }
    __syncthreads();

    int d4 = tid & 15;     // float4 column group
    int rg = tid >> 4;     // 0..15 rows per block per iter
    float4 s = make_float4(0.f, 0.f, 0.f, 0.f);
    float4 q = make_float4(0.f, 0.f, 0.f, 0.f);
    for (int row = blockIdx.x * 16 + rg; row < N; row += gridDim.x * 16) {
        float4 v = ((const float4*)g_h)[(size_t)row * 16 + d4];
        s.x += v.x; s.y += v.y; s.z += v.z; s.w += v.w;
        q.x = fmaf(v.x, v.x, q.x);
        q.y = fmaf(v.y, v.y, q.y);
        q.z = fmaf(v.z, v.z, q.z);
        q.w = fmaf(v.w, v.w, q.w);
    }
    atomicAdd(&sS[d4 * 4 + 0], s.x);
    atomicAdd(&sS[d4 * 4 + 1], s.y);
    atomicAdd(&sS[d4 * 4 + 2], s.z);
    atomicAdd(&sS[d4 * 4 + 3], s.w);
    atomicAdd(&sQ[d4 * 4 + 0], q.x);
    atomicAdd(&sQ[d4 * 4 + 1], q.y);
    atomicAdd(&sQ[d4 * 4 + 2], q.z);
    atomicAdd(&sQ[d4 * 4 + 3], q.w);
    __syncthreads();
    if (tid < DD) {
        atomicAdd(&g_bsum[layer][tid], sS[tid]);
        atomicAdd(&g_bsq[layer][tid],  sQ[tid]);
    }
}

// ============================================================
// K_bn: x_next = (x + gelu(BN(h))) * INV_SQRT2 ; zero agg for next layer
// (R9-proven, unchanged)
// ============================================================
__global__ void k_bn(int xsel, const float* __restrict__ xext,
                     int osel, float* __restrict__ oext,
                     const float* __restrict__ gamma,
                     const float* __restrict__ beta, int layer, int N)
{
    int idx = blockIdx.x * blockDim.x + threadIdx.x;
    if (idx >= N * 16) return;
    const float* xin = sel_in(xsel, xext);
    float* xout = sel_out(osel, oext);

    int q = idx & 15;
    float invN = 1.0f / (float)N;
    float4 hv = ((const float4*)g_h)[idx];
    float4 xv = ((const float4*)xin)[idx];
    float hvv[4] = {hv.x, hv.y, hv.z, hv.w};
    float xvv[4] = {xv.x, xv.y, xv.z, xv.w};
    float o[4];
#pragma unroll
    for (int j = 0; j < 4; j++) {
        int dd = q * 4 + j;
        float mu   = g_bsum[layer][dd] * invN;
        float var  = g_bsq[layer][dd] * invN - mu * mu;
        float rstd = rsqrtf(var + 1e-5f);
        float hn   = (hvv[j] - mu) * rstd * gamma[dd] + beta[dd];
        o[j] = (xvv[j] + gelu_exact(hn)) * INV_SQRT2;
    }
    ((float4*)xout)[idx] = make_float4(o[0], o[1], o[2], o[3]);
    ((float4*)g_agg)[idx] = make_float4(0.f, 0.f, 0.f, 0.f);
}

// ============================================================
// launcher
// ============================================================
extern "C" void kernel_launch(void* const* d_in, const int* in_sizes, int n_in,
                              void* d_out, int out_size)
{
    const float* x0    = (const float*)d_in[0];
    const int*   eidx  = (const int*)  d_in[1];
    const float* eattr = (const float*)d_in[2];
    const float* Wbe   = (const float*)d_in[3];
    const float* bbe   = (const float*)d_in[4];
    const float* epsp  = (const float*)d_in[5];
    const float* W1    = (const float*)d_in[6];
    const float* b1    = (const float*)d_in[7];
    const float* W2    = (const float*)d_in[8];
    const float* b2    = (const float*)d_in[9];
    const float* gamma = (const float*)d_in[10];
    const float* beta  = (const float*)d_in[11];

    int N = in_sizes[0] / DD;
    int E = in_sizes[1] / 2;
    const int* src = eidx;
    const int* dst = eidx + E;

    k_zero<<<(N * 16 + 255) / 256, 256>>>(N);
    k_bond<<<(E + 127) / 128, 256>>>(eattr, Wbe, bbe, E);

    int in_sel[3]  = {0, 1, 2};
    int out_sel[3] = {1, 2, 0};

    int nblk_node = (N * 16 + 255) / 256;
    int nblk_edge = (E * 8 + 255) / 256;
    int nblk_mlp  = (N + 127) / 128;

    for (int l = 0; l < 3; l++) {
        const float* xext = (l == 0) ? x0 : nullptr;
        k_msg <<<nblk_edge, 256>>>(in_sel[l], xext, src, dst, E);
        k_mlp <<<nblk_mlp, 256>>>(in_sel[l], xext,
                                  W1 + (size_t)l * DD * DD, b1 + (size_t)l * DD,
                                  W2 + (size_t)l * DD * DD, b2 + (size_t)l * DD,
                                  epsp, l, N);
        k_stat<<<592, 256>>>(l, N);
        k_bn  <<<nblk_node, 256>>>(in_sel[l], xext, out_sel[l], (float*)d_out,
                                   gamma + (size_t)l * DD, beta + (size_t)l * DD, l, N);
    }
}